// round 1
// baseline (speedup 1.0000x reference)
#include <cuda_runtime.h>
#include <cuda_bf16.h>
#include <math.h>

// ---------------- problem constants ----------------
#define BB   2
#define SS   2048
#define HIDN 2048
#define NH   16
#define NKVH 8
#define DH   128
#define KVD  1024      // NKVH*DH
#define WIN  128
#define TOPK 675       // int(0.33 * 2048)

// ---------------- scratch (static device globals; no allocs) ----------------
__device__ float  g_q[BB * SS * HIDN];
__device__ float  g_k[BB * SS * KVD];
__device__ float  g_v[BB * SS * KVD];
__device__ float  g_attn[BB * SS * HIDN];
__device__ float  g_mean[BB * HIDN];
__device__ double g_mnorm[BB];
__device__ float  g_score[BB * SS];
__device__ int    g_lm[BB * SS];

// ---------------- mean over sequence ----------------
__global__ void mean_kernel(const float* __restrict__ x) {
    int f = blockIdx.x * blockDim.x + threadIdx.x;   // 0..HIDN-1
    int b = blockIdx.y;
    const float* p = x + (size_t)b * SS * HIDN + f;
    double a0 = 0, a1 = 0, a2 = 0, a3 = 0;
    for (int s = 0; s < SS; s += 4) {
        a0 += (double)p[(size_t)(s + 0) * HIDN];
        a1 += (double)p[(size_t)(s + 1) * HIDN];
        a2 += (double)p[(size_t)(s + 2) * HIDN];
        a3 += (double)p[(size_t)(s + 3) * HIDN];
    }
    g_mean[b * HIDN + f] = (float)((a0 + a1 + a2 + a3) / (double)SS);
}

// ---------------- ||mean|| per batch ----------------
__global__ void mnorm_kernel() {
    int b = blockIdx.x, tid = threadIdx.x;
    __shared__ double red[8];
    double acc = 0;
    for (int c = tid; c < HIDN; c += 256) {
        double m = (double)g_mean[b * HIDN + c];
        acc += m * m;
    }
    for (int off = 16; off > 0; off >>= 1)
        acc += __shfl_down_sync(0xffffffffu, acc, off);
    if ((tid & 31) == 0) red[tid >> 5] = acc;
    __syncthreads();
    if (tid == 0) {
        double t = 0;
        for (int w = 0; w < 8; w++) t += red[w];
        g_mnorm[b] = sqrt(t);
    }
}

// ---------------- per-token landmark score ----------------
__global__ void score_kernel(const float* __restrict__ x) {
    int row = blockIdx.x, b = blockIdx.y, tid = threadIdx.x;
    __shared__ double redn[8], redd[8];
    const float* xr = x + ((size_t)b * SS + row) * HIDN;
    const float* mr = g_mean + b * HIDN;
    double n2 = 0, dt = 0;
    for (int c = tid; c < HIDN; c += 256) {
        float xv = xr[c];
        n2 += (double)xv * (double)xv;
        dt += (double)xv * (double)mr[c];
    }
    for (int off = 16; off > 0; off >>= 1) {
        n2 += __shfl_down_sync(0xffffffffu, n2, off);
        dt += __shfl_down_sync(0xffffffffu, dt, off);
    }
    if ((tid & 31) == 0) { redn[tid >> 5] = n2; redd[tid >> 5] = dt; }
    __syncthreads();
    if (tid == 0) {
        double tn = 0, td = 0;
        for (int w = 0; w < 8; w++) { tn += redn[w]; td += redd[w]; }
        double nrm = sqrt(tn);
        double div = -td / (nrm * g_mnorm[b] + 1e-6);
        double sc  = 0.7 * nrm + (1.0 - 0.7) * div;
        g_score[b * SS + row] = (float)sc;
    }
}

// ---------------- exact top-k (bitonic on (score,idx)) + dilation ----------------
__global__ void topk_kernel() {
    int b = blockIdx.x, tid = threadIdx.x;          // 1024 threads
    __shared__ unsigned long long sd[SS];
    __shared__ unsigned char l0[SS], l1[SS];
    for (int i = tid; i < SS; i += 1024) {
        unsigned fb = __float_as_uint(g_score[b * SS + i]);
        unsigned key = (fb & 0x80000000u) ? ~fb : (fb | 0x80000000u);
        sd[i] = ((unsigned long long)key << 32) | (0xFFFFFFFFu - (unsigned)i);
    }
    __syncthreads();
    for (int k2 = 2; k2 <= SS; k2 <<= 1) {
        for (int j = k2 >> 1; j > 0; j >>= 1) {
            for (int i = tid; i < SS; i += 1024) {
                int ixj = i ^ j;
                if (ixj > i) {
                    bool asc = ((i & k2) == 0);
                    unsigned long long a = sd[i], c = sd[ixj];
                    if ((a > c) == asc) { sd[i] = c; sd[ixj] = a; }
                }
            }
            __syncthreads();
        }
    }
    unsigned long long kth = sd[SS - TOPK];   // ascending sort -> k-th largest
    __syncthreads();
    for (int i = tid; i < SS; i += 1024) {
        unsigned fb = __float_as_uint(g_score[b * SS + i]);
        unsigned key = (fb & 0x80000000u) ? ~fb : (fb | 0x80000000u);
        unsigned long long comp = ((unsigned long long)key << 32) | (0xFFFFFFFFu - (unsigned)i);
        l0[i] = (comp >= kth) ? 1 : 0;
    }
    __syncthreads();
    for (int i = tid; i < SS; i += 1024) {
        unsigned char v = l0[i];
        if (i > 0)      v |= l0[i - 1];
        if (i < SS - 1) v |= l0[i + 1];
        l1[i] = v;
    }
    __syncthreads();
    for (int i = tid; i < SS; i += 1024) {
        unsigned char v = l1[i];
        if (i > 0)      v |= l1[i - 1];
        if (i < SS - 1) v |= l1[i + 1];
        g_lm[b * SS + i] = (int)v;
    }
}

// ---------------- fp32 SGEMM: C[M,N] = A[M,K] @ B[K,N] (all row-major, dims % tile == 0)
__global__ void __launch_bounds__(256) sgemm_kernel(
    const float* __restrict__ A, const float* __restrict__ B, float* __restrict__ C,
    int M, int N, int K)
{
    constexpr int BM = 128, BN = 128, BK = 8, TM = 8, TN = 8;
    __shared__ float As[BK][BM];
    __shared__ float Bs[BK][BN];
    int tid = threadIdx.x;
    int trow = tid >> 4, tcol = tid & 15;
    const float* Ab = A + (size_t)blockIdx.y * BM * K;
    const float* Bb = B + (size_t)blockIdx.x * BN;
    float*       Cb = C + (size_t)blockIdx.y * BM * N + (size_t)blockIdx.x * BN;
    int aRow = tid >> 1, aCol = (tid & 1) * 4;
    int bRow = tid >> 5, bCol = (tid & 31) * 4;
    float acc[TM][TN] = {};
    for (int k0 = 0; k0 < K; k0 += BK) {
        float4 av = *(const float4*)(Ab + (size_t)aRow * K + k0 + aCol);
        As[aCol + 0][aRow] = av.x; As[aCol + 1][aRow] = av.y;
        As[aCol + 2][aRow] = av.z; As[aCol + 3][aRow] = av.w;
        *(float4*)&Bs[bRow][bCol] = *(const float4*)(Bb + (size_t)(k0 + bRow) * N + bCol);
        __syncthreads();
#pragma unroll
        for (int kk = 0; kk < BK; kk++) {
            float ar[TM], br[TN];
            *(float4*)&ar[0] = *(float4*)&As[kk][trow * TM];
            *(float4*)&ar[4] = *(float4*)&As[kk][trow * TM + 4];
            *(float4*)&br[0] = *(float4*)&Bs[kk][tcol * TN];
            *(float4*)&br[4] = *(float4*)&Bs[kk][tcol * TN + 4];
#pragma unroll
            for (int i = 0; i < TM; i++)
#pragma unroll
                for (int j = 0; j < TN; j++) acc[i][j] += ar[i] * br[j];
        }
        __syncthreads();
    }
#pragma unroll
    for (int i = 0; i < TM; i++)
#pragma unroll
        for (int j = 0; j < TN; j += 4) {
            *(float4*)(Cb + (size_t)(trow * TM + i) * N + tcol * TN + j) =
                make_float4(acc[i][j], acc[i][j + 1], acc[i][j + 2], acc[i][j + 3]);
        }
}

// ---------------- flash attention with TLS mask (fp32) ----------------
// grid: (SS/64, BB*NH), block 256. smem layout (floats):
//   Qs[64][132] | Ks[128][65] (transposed) | Vs[64][132] | Ps[64][68] | lms int[64]
#define QS_OFF 0
#define KS_OFF (64 * 132)
#define VS_OFF (KS_OFF + 128 * 65)
#define PS_OFF (VS_OFF + 64 * 132)
#define LM_OFF (PS_OFF + 64 * 68)
#define ATTN_SMEM_BYTES ((LM_OFF) * 4 + 64 * 4)

__global__ void __launch_bounds__(256) attn_kernel(
    const float* __restrict__ qb, const float* __restrict__ kb,
    const float* __restrict__ vb, const int* __restrict__ lm,
    float* __restrict__ ob)
{
    extern __shared__ float sm[];
    float* Qs = sm + QS_OFF;
    float* Ks = sm + KS_OFF;
    float* Vs = sm + VS_OFF;
    float* Ps = sm + PS_OFF;
    int*   lms = (int*)(sm + LM_OFF);

    const float NEGINF = __int_as_float(0xff800000);
    int tid = threadIdx.x;
    int tx = tid & 15, ty = tid >> 4;
    int qt = blockIdx.x;
    int bh = blockIdx.y;
    int b = bh / NH, h = bh % NH, kvh = h >> 1;
    int q0 = qt * 64;

    const float* qbase = qb + (size_t)b * SS * HIDN + (size_t)h * DH;
    const float* kbase = kb + (size_t)b * SS * KVD + (size_t)kvh * DH;
    const float* vbase = vb + (size_t)b * SS * KVD + (size_t)kvh * DH;

    // load Q tile [64][128]
#pragma unroll
    for (int it = 0; it < 8; it++) {
        int idx = tid + it * 256;
        int r = idx >> 5, c = (idx & 31) * 4;
        float4 v4 = *(const float4*)(qbase + (size_t)(q0 + r) * HIDN + c);
        float* dst = &Qs[r * 132 + c];
        dst[0] = v4.x; dst[1] = v4.y; dst[2] = v4.z; dst[3] = v4.w;
    }

    float m_i[4], l_i[4], o[4][8];
#pragma unroll
    for (int i = 0; i < 4; i++) {
        m_i[i] = NEGINF; l_i[i] = 0.0f;
#pragma unroll
        for (int jd = 0; jd < 8; jd++) o[i][jd] = 0.0f;
    }

    const float scale = 0.08838834764831845f;  // 1/sqrt(128)

    for (int kt = 0; kt <= qt; kt++) {
        int k0 = kt * 64;
        __syncthreads();   // previous phase-C readers done
        // load K (transposed [d][s]) and V ([s][d]) tiles
#pragma unroll
        for (int it = 0; it < 8; it++) {
            int idx = tid + it * 256;
            int r = idx >> 5, c = (idx & 31) * 4;
            float4 kv4 = *(const float4*)(kbase + (size_t)(k0 + r) * KVD + c);
            Ks[(c + 0) * 65 + r] = kv4.x; Ks[(c + 1) * 65 + r] = kv4.y;
            Ks[(c + 2) * 65 + r] = kv4.z; Ks[(c + 3) * 65 + r] = kv4.w;
            float4 vv4 = *(const float4*)(vbase + (size_t)(k0 + r) * KVD + c);
            *(float4*)&Vs[r * 132 + c] = vv4;
        }
        if (tid < 64) lms[tid] = lm[b * SS + k0 + tid];
        __syncthreads();

        // phase A: S = Q K^T  (thread owns q = ty+16i, k = tx+16j)
        float acc[4][4] = {};
#pragma unroll 4
        for (int d = 0; d < 128; d++) {
            float ar[4], br[4];
#pragma unroll
            for (int i = 0; i < 4; i++) ar[i] = Qs[(ty + 16 * i) * 132 + d];
#pragma unroll
            for (int j = 0; j < 4; j++) br[j] = Ks[d * 65 + tx + 16 * j];
#pragma unroll
            for (int i = 0; i < 4; i++)
#pragma unroll
                for (int j = 0; j < 4; j++) acc[i][j] += ar[i] * br[j];
        }

        // mask + online softmax
#pragma unroll
        for (int i = 0; i < 4; i++) {
            int qg = q0 + ty + 16 * i;
            float s4[4];
            float tmax = NEGINF;
#pragma unroll
            for (int j = 0; j < 4; j++) {
                int kg = k0 + tx + 16 * j;
                bool ok = (kg <= qg) && (((qg - kg) < WIN) || lms[tx + 16 * j]);
                float sv = ok ? acc[i][j] * scale : NEGINF;
                s4[j] = sv;
                tmax = fmaxf(tmax, sv);
            }
#pragma unroll
            for (int mo = 1; mo < 16; mo <<= 1)
                tmax = fmaxf(tmax, __shfl_xor_sync(0xffffffffu, tmax, mo));
            float mnew = fmaxf(m_i[i], tmax);
            float alpha = (mnew == m_i[i]) ? 1.0f : __expf(m_i[i] - mnew);
            float rsum = 0.0f;
#pragma unroll
            for (int j = 0; j < 4; j++) {
                float p = (s4[j] == NEGINF) ? 0.0f : __expf(s4[j] - mnew);
                Ps[(ty + 16 * i) * 68 + tx + 16 * j] = p;
                rsum += p;
            }
#pragma unroll
            for (int mo = 1; mo < 16; mo <<= 1)
                rsum += __shfl_xor_sync(0xffffffffu, rsum, mo);
            l_i[i] = l_i[i] * alpha + rsum;
            m_i[i] = mnew;
#pragma unroll
            for (int jd = 0; jd < 8; jd++) o[i][jd] *= alpha;
        }
        __syncthreads();

        // phase C: O += P @ V  (thread owns q = ty+16i, d = tx+16jd)
#pragma unroll 2
        for (int kv = 0; kv < 64; kv++) {
            float pv[4];
#pragma unroll
            for (int i = 0; i < 4; i++) pv[i] = Ps[(ty + 16 * i) * 68 + kv];
            float vv[8];
#pragma unroll
            for (int jd = 0; jd < 8; jd++) vv[jd] = Vs[kv * 132 + tx + 16 * jd];
#pragma unroll
            for (int i = 0; i < 4; i++)
#pragma unroll
                for (int jd = 0; jd < 8; jd++) o[i][jd] += pv[i] * vv[jd];
        }
    }

    // epilogue
#pragma unroll
    for (int i = 0; i < 4; i++) {
        float inv = 1.0f / l_i[i];
        int qg = q0 + ty + 16 * i;
        float* orow = ob + ((size_t)b * SS + qg) * HIDN + (size_t)h * DH;
#pragma unroll
        for (int jd = 0; jd < 8; jd++) orow[tx + 16 * jd] = o[i][jd] * inv;
    }
}

// ---------------- launch ----------------
extern "C" void kernel_launch(void* const* d_in, const int* in_sizes, int n_in,
                              void* d_out, int out_size)
{
    (void)in_sizes; (void)n_in; (void)out_size;
    const float* x  = (const float*)d_in[0];
    const float* Wq = (const float*)d_in[1];
    const float* Wk = (const float*)d_in[2];
    const float* Wv = (const float*)d_in[3];
    const float* Wo = (const float*)d_in[4];
    float* out = (float*)d_out;

    void *qp, *kp, *vp, *ap, *lmp;
    cudaGetSymbolAddress(&qp,  g_q);
    cudaGetSymbolAddress(&kp,  g_k);
    cudaGetSymbolAddress(&vp,  g_v);
    cudaGetSymbolAddress(&ap,  g_attn);
    cudaGetSymbolAddress(&lmp, g_lm);

    // TLS mask pipeline
    mean_kernel <<<dim3(HIDN / 256, BB), 256>>>(x);
    mnorm_kernel<<<BB, 256>>>();
    score_kernel<<<dim3(SS, BB), 256>>>(x);
    topk_kernel <<<BB, 1024>>>();

    // projections
    sgemm_kernel<<<dim3(HIDN / 128, (BB * SS) / 128), 256>>>(x, Wq, (float*)qp, BB * SS, HIDN, HIDN);
    sgemm_kernel<<<dim3(KVD  / 128, (BB * SS) / 128), 256>>>(x, Wk, (float*)kp, BB * SS, KVD,  HIDN);
    sgemm_kernel<<<dim3(KVD  / 128, (BB * SS) / 128), 256>>>(x, Wv, (float*)vp, BB * SS, KVD,  HIDN);

    // attention
    cudaFuncSetAttribute(attn_kernel, cudaFuncAttributeMaxDynamicSharedMemorySize, ATTN_SMEM_BYTES);
    attn_kernel<<<dim3(SS / 64, BB * NH), 256, ATTN_SMEM_BYTES>>>(
        (const float*)qp, (const float*)kp, (const float*)vp, (const int*)lmp, (float*)ap);

    // output projection
    sgemm_kernel<<<dim3(HIDN / 128, (BB * SS) / 128), 256>>>((const float*)ap, Wo, out, BB * SS, HIDN, HIDN);
}

// round 3
// speedup vs baseline: 1.6614x; 1.6614x over previous
#include <cuda_runtime.h>
#include <cuda_bf16.h>
#include <math.h>
#include <stdint.h>

// ---------------- problem constants ----------------
#define BB   2
#define SS   2048
#define HIDN 2048
#define NH   16
#define NKVH 8
#define DH   128
#define KVD  1024      // NKVH*DH
#define WIN  128
#define TOPK 675       // int(0.33 * 2048)
#define MTOT (BB * SS) // 4096
#define KDIM 2048      // contraction dim of every GEMM

// ---------------- scratch (static device globals; no allocs) ----------------
__device__ float  g_q[MTOT * HIDN];
__device__ float  g_k[MTOT * KVD];
__device__ float  g_v[MTOT * KVD];
__device__ float  g_attn[MTOT * HIDN];
__device__ float  g_mean[BB * HIDN];
__device__ double g_mnorm[BB];
__device__ float  g_score[BB * SS];
__device__ int    g_lm[BB * SS];

// bf16 split operands
__device__ __nv_bfloat16 g_xh[MTOT * HIDN], g_xl[MTOT * HIDN];
__device__ __nv_bfloat16 g_ah[MTOT * HIDN], g_al[MTOT * HIDN];
__device__ __nv_bfloat16 g_wqh[HIDN * KDIM], g_wql[HIDN * KDIM];   // [N, K] K-major
__device__ __nv_bfloat16 g_wkh[KVD  * KDIM], g_wkl[KVD  * KDIM];
__device__ __nv_bfloat16 g_wvh[KVD  * KDIM], g_wvl[KVD  * KDIM];
__device__ __nv_bfloat16 g_woh[HIDN * KDIM], g_wol[HIDN * KDIM];

// ---------------- PTX helpers (sm_80-era only: ldmatrix / mma.sync / cp.async) ----
__device__ __forceinline__ uint32_t s2u(const void* p) {
    uint32_t a;
    asm("{ .reg .u64 t; cvta.to.shared.u64 t, %1; cvt.u32.u64 %0, t; }" : "=r"(a) : "l"(p));
    return a;
}
#define CP16(saddr, gptr) \
    asm volatile("cp.async.cg.shared.global [%0], [%1], 16;" :: "r"(saddr), "l"(gptr))
#define CP_COMMIT() asm volatile("cp.async.commit_group;" ::: "memory")
#define CP_WAIT(n)  asm volatile("cp.async.wait_group %0;" :: "n"(n) : "memory")

#define LDSM4(r0, r1, r2, r3, addr) \
    asm volatile("ldmatrix.sync.aligned.m8n8.x4.shared.b16 {%0,%1,%2,%3}, [%4];" \
                 : "=r"(r0), "=r"(r1), "=r"(r2), "=r"(r3) : "r"(addr))

#define MMA16816(D, a0, a1, a2, a3, b0, b1) \
    asm volatile("mma.sync.aligned.m16n8k16.row.col.f32.bf16.bf16.f32 " \
                 "{%0,%1,%2,%3}, {%4,%5,%6,%7}, {%8,%9}, {%0,%1,%2,%3};" \
                 : "+f"((D)[0]), "+f"((D)[1]), "+f"((D)[2]), "+f"((D)[3]) \
                 : "r"(a0), "r"(a1), "r"(a2), "r"(a3), "r"(b0), "r"(b1))

// ---------------- mean over sequence ----------------
__global__ void mean_kernel(const float* __restrict__ x) {
    int f = blockIdx.x * blockDim.x + threadIdx.x;
    int b = blockIdx.y;
    const float* p = x + (size_t)b * SS * HIDN + f;
    double a0 = 0, a1 = 0, a2 = 0, a3 = 0;
    for (int s = 0; s < SS; s += 4) {
        a0 += (double)p[(size_t)(s + 0) * HIDN];
        a1 += (double)p[(size_t)(s + 1) * HIDN];
        a2 += (double)p[(size_t)(s + 2) * HIDN];
        a3 += (double)p[(size_t)(s + 3) * HIDN];
    }
    g_mean[b * HIDN + f] = (float)((a0 + a1 + a2 + a3) / (double)SS);
}

// ---------------- ||mean|| per batch ----------------
__global__ void mnorm_kernel() {
    int b = blockIdx.x, tid = threadIdx.x;
    __shared__ double red[8];
    double acc = 0;
    for (int c = tid; c < HIDN; c += 256) {
        double m = (double)g_mean[b * HIDN + c];
        acc += m * m;
    }
    for (int off = 16; off > 0; off >>= 1)
        acc += __shfl_down_sync(0xffffffffu, acc, off);
    if ((tid & 31) == 0) red[tid >> 5] = acc;
    __syncthreads();
    if (tid == 0) {
        double t = 0;
        for (int w = 0; w < 8; w++) t += red[w];
        g_mnorm[b] = sqrt(t);
    }
}

// ---------------- per-token landmark score ----------------
__global__ void score_kernel(const float* __restrict__ x) {
    int row = blockIdx.x, b = blockIdx.y, tid = threadIdx.x;
    __shared__ double redn[8], redd[8];
    const float* xr = x + ((size_t)b * SS + row) * HIDN;
    const float* mr = g_mean + b * HIDN;
    double n2 = 0, dt = 0;
    for (int c = tid; c < HIDN; c += 256) {
        float xv = xr[c];
        n2 += (double)xv * (double)xv;
        dt += (double)xv * (double)mr[c];
    }
    for (int off = 16; off > 0; off >>= 1) {
        n2 += __shfl_down_sync(0xffffffffu, n2, off);
        dt += __shfl_down_sync(0xffffffffu, dt, off);
    }
    if ((tid & 31) == 0) { redn[tid >> 5] = n2; redd[tid >> 5] = dt; }
    __syncthreads();
    if (tid == 0) {
        double tn = 0, td = 0;
        for (int w = 0; w < 8; w++) { tn += redn[w]; td += redd[w]; }
        double nrm = sqrt(tn);
        double div = -td / (nrm * g_mnorm[b] + 1e-6);
        double sc  = 0.7 * nrm + (1.0 - 0.7) * div;
        g_score[b * SS + row] = (float)sc;
    }
}

// ---------------- exact top-k (bitonic on (score,idx)) + dilation ----------------
__global__ void topk_kernel() {
    int b = blockIdx.x, tid = threadIdx.x;
    __shared__ unsigned long long sd[SS];
    __shared__ unsigned char l0[SS], l1[SS];
    for (int i = tid; i < SS; i += 1024) {
        unsigned fb = __float_as_uint(g_score[b * SS + i]);
        unsigned key = (fb & 0x80000000u) ? ~fb : (fb | 0x80000000u);
        sd[i] = ((unsigned long long)key << 32) | (0xFFFFFFFFu - (unsigned)i);
    }
    __syncthreads();
    for (int k2 = 2; k2 <= SS; k2 <<= 1) {
        for (int j = k2 >> 1; j > 0; j >>= 1) {
            for (int i = tid; i < SS; i += 1024) {
                int ixj = i ^ j;
                if (ixj > i) {
                    bool asc = ((i & k2) == 0);
                    unsigned long long a = sd[i], c = sd[ixj];
                    if ((a > c) == asc) { sd[i] = c; sd[ixj] = a; }
                }
            }
            __syncthreads();
        }
    }
    unsigned long long kth = sd[SS - TOPK];
    __syncthreads();
    for (int i = tid; i < SS; i += 1024) {
        unsigned fb = __float_as_uint(g_score[b * SS + i]);
        unsigned key = (fb & 0x80000000u) ? ~fb : (fb | 0x80000000u);
        unsigned long long comp = ((unsigned long long)key << 32) | (0xFFFFFFFFu - (unsigned)i);
        l0[i] = (comp >= kth) ? 1 : 0;
    }
    __syncthreads();
    for (int i = tid; i < SS; i += 1024) {
        unsigned char v = l0[i];
        if (i > 0)      v |= l0[i - 1];
        if (i < SS - 1) v |= l0[i + 1];
        l1[i] = v;
    }
    __syncthreads();
    for (int i = tid; i < SS; i += 1024) {
        unsigned char v = l1[i];
        if (i > 0)      v |= l1[i - 1];
        if (i < SS - 1) v |= l1[i + 1];
        g_lm[b * SS + i] = (int)v;
    }
}

// ---------------- split fp32 -> (bf16 hi, bf16 lo) elementwise ----------------
__global__ void xsplit_kernel(const float* __restrict__ X,
                              __nv_bfloat16* __restrict__ Xh,
                              __nv_bfloat16* __restrict__ Xl) {
    int i = blockIdx.x * 256 + threadIdx.x;
    float v = X[i];
    __nv_bfloat16 h = __float2bfloat16(v);
    Xh[i] = h;
    Xl[i] = __float2bfloat16(v - __bfloat162float(h));
}

// ---------------- transpose + split: W[K,N] -> Th/Tl[N,K] bf16 ----------------
__global__ void wsplit_kernel(const float* __restrict__ W,
                              __nv_bfloat16* __restrict__ Th,
                              __nv_bfloat16* __restrict__ Tl, int N) {
    __shared__ float t[32][33];
    int n0 = blockIdx.x * 32, k0 = blockIdx.y * 32;
    int tx = threadIdx.x, ty = threadIdx.y;   // 32 x 8
#pragma unroll
    for (int i = 0; i < 32; i += 8)
        t[ty + i][tx] = W[(size_t)(k0 + ty + i) * N + n0 + tx];
    __syncthreads();
#pragma unroll
    for (int i = 0; i < 32; i += 8) {
        float v = t[tx][ty + i];
        __nv_bfloat16 h = __float2bfloat16(v);
        __nv_bfloat16 l = __float2bfloat16(v - __bfloat162float(h));
        size_t o = (size_t)(n0 + ty + i) * KDIM + k0 + tx;
        Th[o] = h;
        Tl[o] = l;
    }
}

// ---------------- mma.sync bf16 3-term-split GEMM ----------------
// C[M,N] = (Ah+Al)[M,K] @ (Bh+Bl)[N,K]^T  via  AhBh + AlBh + AhBl.
// CTA tile 128x128, BK=64 elts (128B rows, SW128 xor swizzle), cp.async double buffer.
// 8 warps as 2(m) x 4(n); warp tile 64x32 = 4 m-frags x 4 n8-frags of m16n8k16.
#define GBK 64
#define TILEB 16384u                 // one 128x64 bf16 tile
#define BUFB  32768u                 // A tile + B tile
#define GEMM_SMEM_BYTES (2 * BUFB + 1024)
#define NSTEPS 96                    // 3 segments * (2048/64)

__device__ __forceinline__ void load_tiles_async(
    int tid, int s, int m0, int n0,
    const __nv_bfloat16* __restrict__ Ah, const __nv_bfloat16* __restrict__ Al,
    const __nv_bfloat16* __restrict__ Bh, const __nv_bfloat16* __restrict__ Bl,
    uint32_t tbase)
{
    int seg = s >> 5;                    // 0: AhBh, 1: AlBh, 2: AhBl
    int kk  = (s & 31) * GBK;
    const __nv_bfloat16* Ap = (seg == 1) ? Al : Ah;
    const __nv_bfloat16* Bp = (seg == 2) ? Bl : Bh;
    uint32_t bufA = tbase + (uint32_t)(s & 1) * BUFB;
    uint32_t bufB = bufA + TILEB;
#pragma unroll
    for (int j = 0; j < 4; j++) {
        int id = tid + j * 256;          // 0..1023 16B chunks
        int row = id >> 3, c = id & 7;
        uint32_t sw = (uint32_t)((row >> 3) * 1024 + (row & 7) * 128 + ((c ^ (row & 7)) << 4));
        CP16(bufA + sw, (const void*)(Ap + (size_t)(m0 + row) * KDIM + kk + c * 8));
        CP16(bufB + sw, (const void*)(Bp + (size_t)(n0 + row) * KDIM + kk + c * 8));
    }
}

__global__ void __launch_bounds__(256) bf16_gemm_kernel(
    const __nv_bfloat16* __restrict__ Ah, const __nv_bfloat16* __restrict__ Al,
    const __nv_bfloat16* __restrict__ Bh, const __nv_bfloat16* __restrict__ Bl,
    float* __restrict__ C, int N)
{
    extern __shared__ char dsm[];
    uint32_t tbase = (s2u(dsm) + 1023u) & ~1023u;

    int tid = threadIdx.x, lane = tid & 31, wid = tid >> 5;
    int wm = wid >> 2, wn = wid & 3;          // warp grid 2 x 4
    int m0 = blockIdx.y * 128, n0 = blockIdx.x * 128;

    // ldmatrix per-lane addressing (row, swizzle nibble) precompute
    int aR = lane & 15, aC = lane >> 4;       // A: lanes 0-15 rows, 16-31 -> +8 cols
    int bR = ((lane >> 4) << 3) + (lane & 7); // B x4: M0 n0-7,k0 | M1 n0-7,k8 | M2 n8-15,k0 | M3 ..
    int bC = (lane >> 3) & 1;

    uint32_t aOff[4]; int aSw[4];
#pragma unroll
    for (int f = 0; f < 4; f++) {
        int r = wm * 64 + f * 16 + aR;
        aOff[f] = (uint32_t)((r >> 3) * 1024 + (r & 7) * 128);
        aSw[f]  = r & 7;
    }
    uint32_t bOff[2]; int bSw[2];
#pragma unroll
    for (int g = 0; g < 2; g++) {
        int r = wn * 32 + g * 16 + bR;
        bOff[g] = (uint32_t)((r >> 3) * 1024 + (r & 7) * 128);
        bSw[g]  = r & 7;
    }

    float acc[4][4][4];
#pragma unroll
    for (int f = 0; f < 4; f++)
#pragma unroll
        for (int n8 = 0; n8 < 4; n8++)
#pragma unroll
            for (int e = 0; e < 4; e++) acc[f][n8][e] = 0.0f;

    load_tiles_async(tid, 0, m0, n0, Ah, Al, Bh, Bl, tbase);
    CP_COMMIT();

    for (int s = 0; s < NSTEPS; s++) {
        if (s + 1 < NSTEPS) {
            load_tiles_async(tid, s + 1, m0, n0, Ah, Al, Bh, Bl, tbase);
            CP_COMMIT();
            CP_WAIT(1);
        } else {
            CP_WAIT(0);
        }
        __syncthreads();

        uint32_t bufA = tbase + (uint32_t)(s & 1) * BUFB;
        uint32_t bufB = bufA + TILEB;
#pragma unroll
        for (int k16 = 0; k16 < 4; k16++) {
            int ca = k16 * 2 + aC, cb = k16 * 2 + bC;
            uint32_t a[4][4], b[2][4];
#pragma unroll
            for (int f = 0; f < 4; f++)
                LDSM4(a[f][0], a[f][1], a[f][2], a[f][3],
                      bufA + aOff[f] + (uint32_t)((ca ^ aSw[f]) << 4));
#pragma unroll
            for (int g = 0; g < 2; g++)
                LDSM4(b[g][0], b[g][1], b[g][2], b[g][3],
                      bufB + bOff[g] + (uint32_t)((cb ^ bSw[g]) << 4));
#pragma unroll
            for (int f = 0; f < 4; f++)
#pragma unroll
                for (int n8 = 0; n8 < 4; n8++) {
                    int g = n8 >> 1, p = (n8 & 1) * 2;
                    MMA16816(acc[f][n8], a[f][0], a[f][1], a[f][2], a[f][3],
                             b[g][p], b[g][p + 1]);
                }
        }
        __syncthreads();
    }

    // epilogue: c-frag m16n8 -> thread (row = m0+t/4 [+8], col = n0+(t%4)*2)
    int row0 = m0 + wm * 64 + (lane >> 2);
    int col0 = n0 + wn * 32 + (lane & 3) * 2;
#pragma unroll
    for (int f = 0; f < 4; f++)
#pragma unroll
        for (int n8 = 0; n8 < 4; n8++) {
            int r = row0 + f * 16, c = col0 + n8 * 8;
            *(float2*)(C + (size_t)r * N + c)       = make_float2(acc[f][n8][0], acc[f][n8][1]);
            *(float2*)(C + (size_t)(r + 8) * N + c) = make_float2(acc[f][n8][2], acc[f][n8][3]);
        }
}

// ---------------- flash attention with TLS mask (fp32) ----------------
#define QS_OFF 0
#define KS_OFF (64 * 132)
#define VS_OFF (KS_OFF + 128 * 65)
#define PS_OFF (VS_OFF + 64 * 132)
#define LM_OFF (PS_OFF + 64 * 68)
#define ATTN_SMEM_BYTES ((LM_OFF) * 4 + 64 * 4)

__global__ void __launch_bounds__(256) attn_kernel(
    const float* __restrict__ qb, const float* __restrict__ kb,
    const float* __restrict__ vb, const int* __restrict__ lm,
    float* __restrict__ ob)
{
    extern __shared__ float sm[];
    float* Qs = sm + QS_OFF;
    float* Ks = sm + KS_OFF;
    float* Vs = sm + VS_OFF;
    float* Ps = sm + PS_OFF;
    int*   lms = (int*)(sm + LM_OFF);

    const float NEGINF = __int_as_float(0xff800000);
    int tid = threadIdx.x;
    int tx = tid & 15, ty = tid >> 4;
    int qt = blockIdx.x;
    int bh = blockIdx.y;
    int b = bh / NH, h = bh % NH, kvh = h >> 1;
    int q0 = qt * 64;

    const float* qbase = qb + (size_t)b * SS * HIDN + (size_t)h * DH;
    const float* kbase = kb + (size_t)b * SS * KVD + (size_t)kvh * DH;
    const float* vbase = vb + (size_t)b * SS * KVD + (size_t)kvh * DH;

#pragma unroll
    for (int it = 0; it < 8; it++) {
        int idx = tid + it * 256;
        int r = idx >> 5, c = (idx & 31) * 4;
        float4 v4 = *(const float4*)(qbase + (size_t)(q0 + r) * HIDN + c);
        float* dst = &Qs[r * 132 + c];
        dst[0] = v4.x; dst[1] = v4.y; dst[2] = v4.z; dst[3] = v4.w;
    }

    float m_i[4], l_i[4], o[4][8];
#pragma unroll
    for (int i = 0; i < 4; i++) {
        m_i[i] = NEGINF; l_i[i] = 0.0f;
#pragma unroll
        for (int jd = 0; jd < 8; jd++) o[i][jd] = 0.0f;
    }

    const float scale = 0.08838834764831845f;

    for (int kt = 0; kt <= qt; kt++) {
        int k0 = kt * 64;
        __syncthreads();
#pragma unroll
        for (int it = 0; it < 8; it++) {
            int idx = tid + it * 256;
            int r = idx >> 5, c = (idx & 31) * 4;
            float4 kv4 = *(const float4*)(kbase + (size_t)(k0 + r) * KVD + c);
            Ks[(c + 0) * 65 + r] = kv4.x; Ks[(c + 1) * 65 + r] = kv4.y;
            Ks[(c + 2) * 65 + r] = kv4.z; Ks[(c + 3) * 65 + r] = kv4.w;
            float4 vv4 = *(const float4*)(vbase + (size_t)(k0 + r) * KVD + c);
            *(float4*)&Vs[r * 132 + c] = vv4;
        }
        if (tid < 64) lms[tid] = lm[b * SS + k0 + tid];
        __syncthreads();

        float acc[4][4] = {};
#pragma unroll 4
        for (int d = 0; d < 128; d++) {
            float ar[4], br[4];
#pragma unroll
            for (int i = 0; i < 4; i++) ar[i] = Qs[(ty + 16 * i) * 132 + d];
#pragma unroll
            for (int j = 0; j < 4; j++) br[j] = Ks[d * 65 + tx + 16 * j];
#pragma unroll
            for (int i = 0; i < 4; i++)
#pragma unroll
                for (int j = 0; j < 4; j++) acc[i][j] += ar[i] * br[j];
        }

#pragma unroll
        for (int i = 0; i < 4; i++) {
            int qg = q0 + ty + 16 * i;
            float s4[4];
            float tmax = NEGINF;
#pragma unroll
            for (int j = 0; j < 4; j++) {
                int kg = k0 + tx + 16 * j;
                bool ok = (kg <= qg) && (((qg - kg) < WIN) || lms[tx + 16 * j]);
                float sv = ok ? acc[i][j] * scale : NEGINF;
                s4[j] = sv;
                tmax = fmaxf(tmax, sv);
            }
#pragma unroll
            for (int mo = 1; mo < 16; mo <<= 1)
                tmax = fmaxf(tmax, __shfl_xor_sync(0xffffffffu, tmax, mo));
            float mnew = fmaxf(m_i[i], tmax);
            float alpha = (mnew == m_i[i]) ? 1.0f : __expf(m_i[i] - mnew);
            float rsum = 0.0f;
#pragma unroll
            for (int j = 0; j < 4; j++) {
                float p = (s4[j] == NEGINF) ? 0.0f : __expf(s4[j] - mnew);
                Ps[(ty + 16 * i) * 68 + tx + 16 * j] = p;
                rsum += p;
            }
#pragma unroll
            for (int mo = 1; mo < 16; mo <<= 1)
                rsum += __shfl_xor_sync(0xffffffffu, rsum, mo);
            l_i[i] = l_i[i] * alpha + rsum;
            m_i[i] = mnew;
#pragma unroll
            for (int jd = 0; jd < 8; jd++) o[i][jd] *= alpha;
        }
        __syncthreads();

#pragma unroll 2
        for (int kv = 0; kv < 64; kv++) {
            float pv[4];
#pragma unroll
            for (int i = 0; i < 4; i++) pv[i] = Ps[(ty + 16 * i) * 68 + kv];
            float vv[8];
#pragma unroll
            for (int jd = 0; jd < 8; jd++) vv[jd] = Vs[kv * 132 + tx + 16 * jd];
#pragma unroll
            for (int i = 0; i < 4; i++)
#pragma unroll
                for (int jd = 0; jd < 8; jd++) o[i][jd] += pv[i] * vv[jd];
        }
    }

#pragma unroll
    for (int i = 0; i < 4; i++) {
        float inv = 1.0f / l_i[i];
        int qg = q0 + ty + 16 * i;
        float* orow = ob + ((size_t)b * SS + qg) * HIDN + (size_t)h * DH;
#pragma unroll
        for (int jd = 0; jd < 8; jd++) orow[tx + 16 * jd] = o[i][jd] * inv;
    }
}

// ---------------- launch ----------------
extern "C" void kernel_launch(void* const* d_in, const int* in_sizes, int n_in,
                              void* d_out, int out_size)
{
    (void)in_sizes; (void)n_in; (void)out_size;
    const float* x  = (const float*)d_in[0];
    const float* Wq = (const float*)d_in[1];
    const float* Wk = (const float*)d_in[2];
    const float* Wv = (const float*)d_in[3];
    const float* Wo = (const float*)d_in[4];
    float* out = (float*)d_out;

    void *qp, *kp, *vp, *ap, *lmp;
    void *xh, *xl, *ah, *al;
    void *wqh, *wql, *wkh, *wkl, *wvh, *wvl, *woh, *wol;
    cudaGetSymbolAddress(&qp,  g_q);
    cudaGetSymbolAddress(&kp,  g_k);
    cudaGetSymbolAddress(&vp,  g_v);
    cudaGetSymbolAddress(&ap,  g_attn);
    cudaGetSymbolAddress(&lmp, g_lm);
    cudaGetSymbolAddress(&xh, g_xh);   cudaGetSymbolAddress(&xl, g_xl);
    cudaGetSymbolAddress(&ah, g_ah);   cudaGetSymbolAddress(&al, g_al);
    cudaGetSymbolAddress(&wqh, g_wqh); cudaGetSymbolAddress(&wql, g_wql);
    cudaGetSymbolAddress(&wkh, g_wkh); cudaGetSymbolAddress(&wkl, g_wkl);
    cudaGetSymbolAddress(&wvh, g_wvh); cudaGetSymbolAddress(&wvl, g_wvl);
    cudaGetSymbolAddress(&woh, g_woh); cudaGetSymbolAddress(&wol, g_wol);

    // TLS mask pipeline
    mean_kernel <<<dim3(HIDN / 256, BB), 256>>>(x);
    mnorm_kernel<<<BB, 256>>>();
    score_kernel<<<dim3(SS, BB), 256>>>(x);
    topk_kernel <<<BB, 1024>>>();

    // operand prep: split x, transpose+split weights
    xsplit_kernel<<<(MTOT * HIDN) / 256, 256>>>(x, (__nv_bfloat16*)xh, (__nv_bfloat16*)xl);
    wsplit_kernel<<<dim3(HIDN / 32, KDIM / 32), dim3(32, 8)>>>(Wq, (__nv_bfloat16*)wqh, (__nv_bfloat16*)wql, HIDN);
    wsplit_kernel<<<dim3(KVD  / 32, KDIM / 32), dim3(32, 8)>>>(Wk, (__nv_bfloat16*)wkh, (__nv_bfloat16*)wkl, KVD);
    wsplit_kernel<<<dim3(KVD  / 32, KDIM / 32), dim3(32, 8)>>>(Wv, (__nv_bfloat16*)wvh, (__nv_bfloat16*)wvl, KVD);
    wsplit_kernel<<<dim3(HIDN / 32, KDIM / 32), dim3(32, 8)>>>(Wo, (__nv_bfloat16*)woh, (__nv_bfloat16*)wol, HIDN);

    cudaFuncSetAttribute(bf16_gemm_kernel, cudaFuncAttributeMaxDynamicSharedMemorySize, GEMM_SMEM_BYTES);

    // projections (tensor cores via mma.sync)
    bf16_gemm_kernel<<<dim3(HIDN / 128, MTOT / 128), 256, GEMM_SMEM_BYTES>>>(
        (const __nv_bfloat16*)xh, (const __nv_bfloat16*)xl,
        (const __nv_bfloat16*)wqh, (const __nv_bfloat16*)wql, (float*)qp, HIDN);
    bf16_gemm_kernel<<<dim3(KVD / 128, MTOT / 128), 256, GEMM_SMEM_BYTES>>>(
        (const __nv_bfloat16*)xh, (const __nv_bfloat16*)xl,
        (const __nv_bfloat16*)wkh, (const __nv_bfloat16*)wkl, (float*)kp, KVD);
    bf16_gemm_kernel<<<dim3(KVD / 128, MTOT / 128), 256, GEMM_SMEM_BYTES>>>(
        (const __nv_bfloat16*)xh, (const __nv_bfloat16*)xl,
        (const __nv_bfloat16*)wvh, (const __nv_bfloat16*)wvl, (float*)vp, KVD);

    // attention (fp32 flash, unchanged this round)
    cudaFuncSetAttribute(attn_kernel, cudaFuncAttributeMaxDynamicSharedMemorySize, ATTN_SMEM_BYTES);
    attn_kernel<<<dim3(SS / 64, BB * NH), 256, ATTN_SMEM_BYTES>>>(
        (const float*)qp, (const float*)kp, (const float*)vp, (const int*)lmp, (float*)ap);

    // split attention output, then output projection
    xsplit_kernel<<<(MTOT * HIDN) / 256, 256>>>((const float*)ap, (__nv_bfloat16*)ah, (__nv_bfloat16*)al);
    bf16_gemm_kernel<<<dim3(HIDN / 128, MTOT / 128), 256, GEMM_SMEM_BYTES>>>(
        (const __nv_bfloat16*)ah, (const __nv_bfloat16*)al,
        (const __nv_bfloat16*)woh, (const __nv_bfloat16*)wol, out, HIDN);
}

// round 4
// speedup vs baseline: 2.8507x; 1.7159x over previous
#include <cuda_runtime.h>
#include <cuda_bf16.h>
#include <math.h>
#include <stdint.h>

// ---------------- problem constants ----------------
#define BB   2
#define SS   2048
#define HIDN 2048
#define NH   16
#define NKVH 8
#define DH   128
#define KVD  1024
#define WIN  128
#define TOPK 675
#define MTOT (BB * SS)
#define KDIM 2048

// ---------------- scratch (static device globals; no allocs) ----------------
__device__ float  g_mean[BB * HIDN];
__device__ double g_mnorm[BB];
__device__ float  g_score[BB * SS];
__device__ int    g_lm[BB * SS];

__device__ __nv_bfloat16 g_xh[MTOT * HIDN], g_xl[MTOT * HIDN];
__device__ __nv_bfloat16 g_qh[MTOT * HIDN], g_ql[MTOT * HIDN];
__device__ __nv_bfloat16 g_kh[MTOT * KVD],  g_kl[MTOT * KVD];
__device__ __nv_bfloat16 g_vh[MTOT * KVD],  g_vl[MTOT * KVD];
__device__ __nv_bfloat16 g_ah[MTOT * HIDN], g_al[MTOT * HIDN];
__device__ __nv_bfloat16 g_wqh[HIDN * KDIM], g_wql[HIDN * KDIM];
__device__ __nv_bfloat16 g_wkh[KVD  * KDIM], g_wkl[KVD  * KDIM];
__device__ __nv_bfloat16 g_wvh[KVD  * KDIM], g_wvl[KVD  * KDIM];
__device__ __nv_bfloat16 g_woh[HIDN * KDIM], g_wol[HIDN * KDIM];

// ---------------- PTX helpers ----------------
__device__ __forceinline__ uint32_t s2u(const void* p) {
    uint32_t a;
    asm("{ .reg .u64 t; cvta.to.shared.u64 t, %1; cvt.u32.u64 %0, t; }" : "=r"(a) : "l"(p));
    return a;
}
#define CP16(saddr, gptr) \
    asm volatile("cp.async.cg.shared.global [%0], [%1], 16;" :: "r"(saddr), "l"(gptr))
#define CP_COMMIT() asm volatile("cp.async.commit_group;" ::: "memory")
#define CP_WAIT(n)  asm volatile("cp.async.wait_group %0;" :: "n"(n) : "memory")

#define LDSM4(r0, r1, r2, r3, addr) \
    asm volatile("ldmatrix.sync.aligned.m8n8.x4.shared.b16 {%0,%1,%2,%3}, [%4];" \
                 : "=r"(r0), "=r"(r1), "=r"(r2), "=r"(r3) : "r"(addr))
#define LDSM4T(r0, r1, r2, r3, addr) \
    asm volatile("ldmatrix.sync.aligned.m8n8.x4.trans.shared.b16 {%0,%1,%2,%3}, [%4];" \
                 : "=r"(r0), "=r"(r1), "=r"(r2), "=r"(r3) : "r"(addr))

#define MMA16816(D, a0, a1, a2, a3, b0, b1) \
    asm volatile("mma.sync.aligned.m16n8k16.row.col.f32.bf16.bf16.f32 " \
                 "{%0,%1,%2,%3}, {%4,%5,%6,%7}, {%8,%9}, {%0,%1,%2,%3};" \
                 : "+f"((D)[0]), "+f"((D)[1]), "+f"((D)[2]), "+f"((D)[3]) \
                 : "r"(a0), "r"(a1), "r"(a2), "r"(a3), "r"(b0), "r"(b1))

__device__ __forceinline__ uint32_t pack_bf16(float lo, float hi) {
    uint32_t r;
    asm("cvt.rn.bf16x2.f32 %0, %1, %2;" : "=r"(r) : "f"(hi), "f"(lo));
    return r;
}
__device__ __forceinline__ void store_split2(__nv_bfloat16* Hp, __nv_bfloat16* Lp,
                                             float v0, float v1) {
    __nv_bfloat16 h0 = __float2bfloat16(v0), h1 = __float2bfloat16(v1);
    __nv_bfloat16 l0 = __float2bfloat16(v0 - __bfloat162float(h0));
    __nv_bfloat16 l1 = __float2bfloat16(v1 - __bfloat162float(h1));
    *(__nv_bfloat162*)Hp = __halves2bfloat162(h0, h1);
    *(__nv_bfloat162*)Lp = __halves2bfloat162(l0, l1);
}

// ---------------- mean over sequence ----------------
__global__ void mean_kernel(const float* __restrict__ x) {
    int f = blockIdx.x * blockDim.x + threadIdx.x;
    int b = blockIdx.y;
    const float* p = x + (size_t)b * SS * HIDN + f;
    double a0 = 0, a1 = 0, a2 = 0, a3 = 0;
    for (int s = 0; s < SS; s += 4) {
        a0 += (double)p[(size_t)(s + 0) * HIDN];
        a1 += (double)p[(size_t)(s + 1) * HIDN];
        a2 += (double)p[(size_t)(s + 2) * HIDN];
        a3 += (double)p[(size_t)(s + 3) * HIDN];
    }
    g_mean[b * HIDN + f] = (float)((a0 + a1 + a2 + a3) / (double)SS);
}

// ---------------- ||mean|| per batch ----------------
__global__ void mnorm_kernel() {
    int b = blockIdx.x, tid = threadIdx.x;
    __shared__ double red[8];
    double acc = 0;
    for (int c = tid; c < HIDN; c += 256) {
        double m = (double)g_mean[b * HIDN + c];
        acc += m * m;
    }
    for (int off = 16; off > 0; off >>= 1)
        acc += __shfl_down_sync(0xffffffffu, acc, off);
    if ((tid & 31) == 0) red[tid >> 5] = acc;
    __syncthreads();
    if (tid == 0) {
        double t = 0;
        for (int w = 0; w < 8; w++) t += red[w];
        g_mnorm[b] = sqrt(t);
    }
}

// ---------------- per-token landmark score ----------------
__global__ void score_kernel(const float* __restrict__ x) {
    int row = blockIdx.x, b = blockIdx.y, tid = threadIdx.x;
    __shared__ double redn[8], redd[8];
    const float* xr = x + ((size_t)b * SS + row) * HIDN;
    const float* mr = g_mean + b * HIDN;
    double n2 = 0, dt = 0;
    for (int c = tid; c < HIDN; c += 256) {
        float xv = xr[c];
        n2 += (double)xv * (double)xv;
        dt += (double)xv * (double)mr[c];
    }
    for (int off = 16; off > 0; off >>= 1) {
        n2 += __shfl_down_sync(0xffffffffu, n2, off);
        dt += __shfl_down_sync(0xffffffffu, dt, off);
    }
    if ((tid & 31) == 0) { redn[tid >> 5] = n2; redd[tid >> 5] = dt; }
    __syncthreads();
    if (tid == 0) {
        double tn = 0, td = 0;
        for (int w = 0; w < 8; w++) { tn += redn[w]; td += redd[w]; }
        double nrm = sqrt(tn);
        double div = -td / (nrm * g_mnorm[b] + 1e-6);
        double sc  = 0.7 * nrm + (1.0 - 0.7) * div;
        g_score[b * SS + row] = (float)sc;
    }
}

// ---------------- exact top-k (bitonic) + dilation ----------------
__global__ void topk_kernel() {
    int b = blockIdx.x, tid = threadIdx.x;
    __shared__ unsigned long long sd[SS];
    __shared__ unsigned char l0[SS], l1[SS];
    for (int i = tid; i < SS; i += 1024) {
        unsigned fb = __float_as_uint(g_score[b * SS + i]);
        unsigned key = (fb & 0x80000000u) ? ~fb : (fb | 0x80000000u);
        sd[i] = ((unsigned long long)key << 32) | (0xFFFFFFFFu - (unsigned)i);
    }
    __syncthreads();
    for (int k2 = 2; k2 <= SS; k2 <<= 1) {
        for (int j = k2 >> 1; j > 0; j >>= 1) {
            for (int i = tid; i < SS; i += 1024) {
                int ixj = i ^ j;
                if (ixj > i) {
                    bool asc = ((i & k2) == 0);
                    unsigned long long a = sd[i], c = sd[ixj];
                    if ((a > c) == asc) { sd[i] = c; sd[ixj] = a; }
                }
            }
            __syncthreads();
        }
    }
    unsigned long long kth = sd[SS - TOPK];
    __syncthreads();
    for (int i = tid; i < SS; i += 1024) {
        unsigned fb = __float_as_uint(g_score[b * SS + i]);
        unsigned key = (fb & 0x80000000u) ? ~fb : (fb | 0x80000000u);
        unsigned long long comp = ((unsigned long long)key << 32) | (0xFFFFFFFFu - (unsigned)i);
        l0[i] = (comp >= kth) ? 1 : 0;
    }
    __syncthreads();
    for (int i = tid; i < SS; i += 1024) {
        unsigned char v = l0[i];
        if (i > 0)      v |= l0[i - 1];
        if (i < SS - 1) v |= l0[i + 1];
        l1[i] = v;
    }
    __syncthreads();
    for (int i = tid; i < SS; i += 1024) {
        unsigned char v = l1[i];
        if (i > 0)      v |= l1[i - 1];
        if (i < SS - 1) v |= l1[i + 1];
        g_lm[b * SS + i] = (int)v;
    }
}

// ---------------- split fp32 -> (bf16 hi, bf16 lo) ----------------
__global__ void xsplit_kernel(const float* __restrict__ X,
                              __nv_bfloat16* __restrict__ Xh,
                              __nv_bfloat16* __restrict__ Xl) {
    int i = blockIdx.x * 256 + threadIdx.x;
    float v = X[i];
    __nv_bfloat16 h = __float2bfloat16(v);
    Xh[i] = h;
    Xl[i] = __float2bfloat16(v - __bfloat162float(h));
}

// ---------------- transpose + split: W[K,N] -> Th/Tl[N,K] bf16 ----------------
__global__ void wsplit_kernel(const float* __restrict__ W,
                              __nv_bfloat16* __restrict__ Th,
                              __nv_bfloat16* __restrict__ Tl, int N) {
    __shared__ float t[32][33];
    int n0 = blockIdx.x * 32, k0 = blockIdx.y * 32;
    int tx = threadIdx.x, ty = threadIdx.y;
#pragma unroll
    for (int i = 0; i < 32; i += 8)
        t[ty + i][tx] = W[(size_t)(k0 + ty + i) * N + n0 + tx];
    __syncthreads();
#pragma unroll
    for (int i = 0; i < 32; i += 8) {
        float v = t[tx][ty + i];
        __nv_bfloat16 h = __float2bfloat16(v);
        __nv_bfloat16 l = __float2bfloat16(v - __bfloat162float(h));
        size_t o = (size_t)(n0 + ty + i) * KDIM + k0 + tx;
        Th[o] = h;
        Tl[o] = l;
    }
}

// ---------------- mma.sync bf16 3-term-split GEMM (3-stage cp.async) ----------------
#define GBK 64
#define TILEB 16384u
#define BUFB  32768u
#define GEMM_SMEM_BYTES (3 * 32768 + 1024)
#define NSTEPS 96

__device__ __forceinline__ void load_tiles_async(
    int tid, int s, int m0, int n0,
    const __nv_bfloat16* __restrict__ Ah, const __nv_bfloat16* __restrict__ Al,
    const __nv_bfloat16* __restrict__ Bh, const __nv_bfloat16* __restrict__ Bl,
    uint32_t bufA)
{
    int seg = s >> 5;
    int kk  = (s & 31) * GBK;
    const __nv_bfloat16* Ap = (seg == 1) ? Al : Ah;
    const __nv_bfloat16* Bp = (seg == 2) ? Bl : Bh;
    uint32_t bufB = bufA + TILEB;
#pragma unroll
    for (int j = 0; j < 4; j++) {
        int id = tid + j * 256;
        int row = id >> 3, c = id & 7;
        uint32_t sw = (uint32_t)((row >> 3) * 1024 + (row & 7) * 128 + ((c ^ (row & 7)) << 4));
        CP16(bufA + sw, (const void*)(Ap + (size_t)(m0 + row) * KDIM + kk + c * 8));
        CP16(bufB + sw, (const void*)(Bp + (size_t)(n0 + row) * KDIM + kk + c * 8));
    }
}

template<bool SPLIT>
__global__ void __launch_bounds__(256) bf16_gemm_kernel(
    const __nv_bfloat16* __restrict__ Ah, const __nv_bfloat16* __restrict__ Al,
    const __nv_bfloat16* __restrict__ Bh, const __nv_bfloat16* __restrict__ Bl,
    float* __restrict__ Cf, __nv_bfloat16* __restrict__ Ch, __nv_bfloat16* __restrict__ Cl,
    int N)
{
    extern __shared__ char dsm[];
    uint32_t tbase = (s2u(dsm) + 1023u) & ~1023u;

    int tid = threadIdx.x, lane = tid & 31, wid = tid >> 5;
    int wm = wid >> 2, wn = wid & 3;
    int m0 = blockIdx.y * 128, n0 = blockIdx.x * 128;

    int aR = lane & 15, aC = lane >> 4;
    int bR = ((lane >> 4) << 3) + (lane & 7);
    int bC = (lane >> 3) & 1;

    uint32_t aOff[4]; int aSw[4];
#pragma unroll
    for (int f = 0; f < 4; f++) {
        int r = wm * 64 + f * 16 + aR;
        aOff[f] = (uint32_t)((r >> 3) * 1024 + (r & 7) * 128);
        aSw[f]  = r & 7;
    }
    uint32_t bOff[2]; int bSw[2];
#pragma unroll
    for (int g = 0; g < 2; g++) {
        int r = wn * 32 + g * 16 + bR;
        bOff[g] = (uint32_t)((r >> 3) * 1024 + (r & 7) * 128);
        bSw[g]  = r & 7;
    }

    float acc[4][4][4];
#pragma unroll
    for (int f = 0; f < 4; f++)
#pragma unroll
        for (int n8 = 0; n8 < 4; n8++)
#pragma unroll
            for (int e = 0; e < 4; e++) acc[f][n8][e] = 0.0f;

    load_tiles_async(tid, 0, m0, n0, Ah, Al, Bh, Bl, tbase);
    CP_COMMIT();
    load_tiles_async(tid, 1, m0, n0, Ah, Al, Bh, Bl, tbase + BUFB);
    CP_COMMIT();

    int bidx = 0, pre = 2;
    for (int s = 0; s < NSTEPS; s++) {
        if (s == NSTEPS - 1) { CP_WAIT(0); } else { CP_WAIT(1); }
        __syncthreads();
        if (s + 2 < NSTEPS) {
            load_tiles_async(tid, s + 2, m0, n0, Ah, Al, Bh, Bl, tbase + (uint32_t)pre * BUFB);
            CP_COMMIT();
        }

        uint32_t bufA = tbase + (uint32_t)bidx * BUFB;
        uint32_t bufB = bufA + TILEB;
#pragma unroll
        for (int k16 = 0; k16 < 4; k16++) {
            int ca = k16 * 2 + aC, cb = k16 * 2 + bC;
            uint32_t a[4][4], b[2][4];
#pragma unroll
            for (int f = 0; f < 4; f++)
                LDSM4(a[f][0], a[f][1], a[f][2], a[f][3],
                      bufA + aOff[f] + (uint32_t)((ca ^ aSw[f]) << 4));
#pragma unroll
            for (int g = 0; g < 2; g++)
                LDSM4(b[g][0], b[g][1], b[g][2], b[g][3],
                      bufB + bOff[g] + (uint32_t)((cb ^ bSw[g]) << 4));
#pragma unroll
            for (int f = 0; f < 4; f++)
#pragma unroll
                for (int n8 = 0; n8 < 4; n8++) {
                    int g = n8 >> 1, p = (n8 & 1) * 2;
                    MMA16816(acc[f][n8], a[f][0], a[f][1], a[f][2], a[f][3],
                             b[g][p], b[g][p + 1]);
                }
        }
        if (++bidx == 3) bidx = 0;
        if (++pre == 3) pre = 0;
    }

    int row0 = m0 + wm * 64 + (lane >> 2);
    int col0 = n0 + wn * 32 + (lane & 3) * 2;
#pragma unroll
    for (int f = 0; f < 4; f++)
#pragma unroll
        for (int n8 = 0; n8 < 4; n8++) {
            int r = row0 + f * 16, c = col0 + n8 * 8;
            if (SPLIT) {
                store_split2(Ch + (size_t)r * N + c, Cl + (size_t)r * N + c,
                             acc[f][n8][0], acc[f][n8][1]);
                store_split2(Ch + (size_t)(r + 8) * N + c, Cl + (size_t)(r + 8) * N + c,
                             acc[f][n8][2], acc[f][n8][3]);
            } else {
                *(float2*)(Cf + (size_t)r * N + c)       = make_float2(acc[f][n8][0], acc[f][n8][1]);
                *(float2*)(Cf + (size_t)(r + 8) * N + c) = make_float2(acc[f][n8][2], acc[f][n8][3]);
            }
        }
}

// ---------------- split-bf16 mma flash attention ----------------
// q-tile 128, k-tile 64. 8 warps, warp = 16 q rows. 3-term split on QK and PV.
// smem: Qh 32K | Ql 32K | 2 x KV buf (Kh 16K | Kl 16K | Vh 16K | Vl 16K) | lm
#define SM_QH 0u
#define SM_QL 32768u
#define SM_KV 65536u
#define SM_LM 196608u
#define ATT_SMEM (196608 + 512 + 1024)
#define NEGINF __int_as_float(0xff800000)

__device__ __forceinline__ void att_load_kv(
    int tid, uint32_t base, int bsel, int k0,
    const __nv_bfloat16* __restrict__ khb, const __nv_bfloat16* __restrict__ klb,
    const __nv_bfloat16* __restrict__ vhb, const __nv_bfloat16* __restrict__ vlb,
    const int* __restrict__ lmb)
{
    uint32_t kb = base + SM_KV + (uint32_t)bsel * 65536u;
#pragma unroll
    for (int i = 0; i < 4; i++) {
        int id = tid + i * 256;
        int r = id >> 4, c16 = id & 15, sub = c16 >> 3, c = c16 & 7;
        uint32_t sw = (uint32_t)(sub * 8192 + (r >> 3) * 1024 + (r & 7) * 128 + ((c ^ (r & 7)) << 4));
        size_t so = (size_t)(k0 + r) * KVD + sub * 64 + c * 8;
        CP16(kb + sw,          (const void*)(khb + so));
        CP16(kb + 16384u + sw, (const void*)(klb + so));
        CP16(kb + 32768u + sw, (const void*)(vhb + so));
        CP16(kb + 49152u + sw, (const void*)(vlb + so));
    }
    if (tid < 16)
        CP16(base + SM_LM + (uint32_t)bsel * 256u + (uint32_t)tid * 16u,
             (const void*)(lmb + k0 + tid * 4));
}

__global__ void __launch_bounds__(256) attn_mma_kernel(
    const __nv_bfloat16* __restrict__ qh_g, const __nv_bfloat16* __restrict__ ql_g,
    const __nv_bfloat16* __restrict__ kh_g, const __nv_bfloat16* __restrict__ kl_g,
    const __nv_bfloat16* __restrict__ vh_g, const __nv_bfloat16* __restrict__ vl_g,
    const int* __restrict__ lm,
    __nv_bfloat16* __restrict__ ah_g, __nv_bfloat16* __restrict__ al_g)
{
    extern __shared__ char dsm[];
    uint32_t base = (s2u(dsm) + 1023u) & ~1023u;
    uint32_t pad  = base - s2u(dsm);

    int tid = threadIdx.x, lane = tid & 31, wid = tid >> 5;
    int qt = blockIdx.x, bh = blockIdx.y;
    int b = bh >> 4, h = bh & 15, kvh = h >> 1;
    int q0 = qt * 128;

    const __nv_bfloat16* qhb = qh_g + ((size_t)(b * SS + q0)) * HIDN + h * DH;
    const __nv_bfloat16* qlb = ql_g + ((size_t)(b * SS + q0)) * HIDN + h * DH;
    const __nv_bfloat16* khb = kh_g + ((size_t)b * SS) * KVD + kvh * DH;
    const __nv_bfloat16* klb = kl_g + ((size_t)b * SS) * KVD + kvh * DH;
    const __nv_bfloat16* vhb = vh_g + ((size_t)b * SS) * KVD + kvh * DH;
    const __nv_bfloat16* vlb = vl_g + ((size_t)b * SS) * KVD + kvh * DH;
    const int* lmb = lm + b * SS;

    // load Q tiles (hi+lo), group 0
#pragma unroll
    for (int i = 0; i < 8; i++) {
        int id = tid + i * 256;
        int r = id >> 4, c16 = id & 15, sub = c16 >> 3, c = c16 & 7;
        uint32_t sw = (uint32_t)(sub * 16384 + (r >> 3) * 1024 + (r & 7) * 128 + ((c ^ (r & 7)) << 4));
        size_t so = (size_t)r * HIDN + sub * 64 + c * 8;
        CP16(base + SM_QH + sw, (const void*)(qhb + so));
        CP16(base + SM_QL + sw, (const void*)(qlb + so));
    }
    CP_COMMIT();
    att_load_kv(tid, base, 0, 0, khb, klb, vhb, vlb, lmb);
    CP_COMMIT();

    float m0r = NEGINF, m1r = NEGINF, l0r = 0.0f, l1r = 0.0f;
    float oacc[16][4];
#pragma unroll
    for (int jo = 0; jo < 16; jo++)
#pragma unroll
        for (int e = 0; e < 4; e++) oacc[jo][e] = 0.0f;

    const float scale = 0.08838834764831845f;
    int qg0 = q0 + wid * 16 + (lane >> 2);
    int qg1 = qg0 + 8;
    int qmaxw = q0 + wid * 16 + 15;

    // ldmatrix lane addressing
    int aR = wid * 16 + (lane & 15);
    uint32_t aOff = (uint32_t)((aR >> 3) * 1024 + (aR & 7) * 128);
    int aSw = aR & 7;
    int bRr = ((lane >> 4) << 3) + (lane & 7);
    int rV0 = (lane & 7) + ((lane >> 3) & 1) * 8;

    int nkt = 2 * qt + 2;
    for (int kt = 0; kt < nkt; kt++) {
        int k0 = kt * 64, bsel = kt & 1;
        CP_WAIT(0);
        __syncthreads();
        if (kt + 1 < nkt) {
            att_load_kv(tid, base, bsel ^ 1, (kt + 1) * 64, khb, klb, vhb, vlb, lmb);
            CP_COMMIT();
        }
        if (k0 > qmaxw) continue;

        uint32_t kvb = base + SM_KV + (uint32_t)bsel * 65536u;
        const int* lms = (const int*)(dsm + pad + SM_LM + bsel * 256);
        int kmax = qmaxw - k0;
        int jmax = min(7, kmax >> 3);
        int gmax = jmax >> 1;

        // ---- S = QK^T (3 split terms) ----
        float sacc[8][4];
#pragma unroll
        for (int j = 0; j < 8; j++)
#pragma unroll
            for (int e = 0; e < 4; e++) sacc[j][e] = 0.0f;

        uint32_t qh_s = base + SM_QH, ql_s = base + SM_QL;
        uint32_t kh_s = kvb, kl_s = kvb + 16384u;
#pragma unroll
        for (int k16 = 0; k16 < 8; k16++) {
            int sub = k16 >> 2;
            int ca = (k16 & 3) * 2 + (lane >> 4);
            uint32_t aaddr = (uint32_t)(sub * 16384) + aOff + (uint32_t)((ca ^ aSw) << 4);
            uint32_t ah0, ah1, ah2, ah3, al0_, al1_, al2_, al3_;
            LDSM4(ah0, ah1, ah2, ah3, qh_s + aaddr);
            LDSM4(al0_, al1_, al2_, al3_, ql_s + aaddr);
            int cb = (k16 & 3) * 2 + ((lane >> 3) & 1);
            uint32_t bhm[4][4], blm[4][4];
#pragma unroll
            for (int g = 0; g < 4; g++) {
                if (g <= gmax) {
                    int r = g * 16 + bRr;
                    uint32_t off = (uint32_t)(sub * 8192 + (r >> 3) * 1024 + (r & 7) * 128 +
                                              ((cb ^ (r & 7)) << 4));
                    LDSM4(bhm[g][0], bhm[g][1], bhm[g][2], bhm[g][3], kh_s + off);
                    LDSM4(blm[g][0], blm[g][1], blm[g][2], blm[g][3], kl_s + off);
                }
            }
#pragma unroll
            for (int j = 0; j < 8; j++) {
                if (j <= jmax) {
                    int g = j >> 1, p = (j & 1) * 2;
                    MMA16816(sacc[j], ah0, ah1, ah2, ah3, bhm[g][p], bhm[g][p + 1]);
                    MMA16816(sacc[j], al0_, al1_, al2_, al3_, bhm[g][p], bhm[g][p + 1]);
                    MMA16816(sacc[j], ah0, ah1, ah2, ah3, blm[g][p], blm[g][p + 1]);
                }
            }
        }

        // ---- mask + online softmax ----
        float tmax0 = NEGINF, tmax1 = NEGINF;
        int colb = (lane & 3) * 2;
#pragma unroll
        for (int j = 0; j < 8; j++) {
            if (j <= jmax) {
                int kk0 = j * 8 + colb, kk1 = kk0 + 1;
                int kg0 = k0 + kk0, kg1 = kg0 + 1;
                int lmv0 = lms[kk0], lmv1 = lms[kk1];
                float sv;
                bool ok;
                ok = (kg0 <= qg0) && (((qg0 - kg0) < WIN) || lmv0);
                sv = ok ? sacc[j][0] * scale : NEGINF; sacc[j][0] = sv; tmax0 = fmaxf(tmax0, sv);
                ok = (kg1 <= qg0) && (((qg0 - kg1) < WIN) || lmv1);
                sv = ok ? sacc[j][1] * scale : NEGINF; sacc[j][1] = sv; tmax0 = fmaxf(tmax0, sv);
                ok = (kg0 <= qg1) && (((qg1 - kg0) < WIN) || lmv0);
                sv = ok ? sacc[j][2] * scale : NEGINF; sacc[j][2] = sv; tmax1 = fmaxf(tmax1, sv);
                ok = (kg1 <= qg1) && (((qg1 - kg1) < WIN) || lmv1);
                sv = ok ? sacc[j][3] * scale : NEGINF; sacc[j][3] = sv; tmax1 = fmaxf(tmax1, sv);
            }
        }
        tmax0 = fmaxf(tmax0, __shfl_xor_sync(0xffffffffu, tmax0, 1));
        tmax0 = fmaxf(tmax0, __shfl_xor_sync(0xffffffffu, tmax0, 2));
        tmax1 = fmaxf(tmax1, __shfl_xor_sync(0xffffffffu, tmax1, 1));
        tmax1 = fmaxf(tmax1, __shfl_xor_sync(0xffffffffu, tmax1, 2));

        float mn0 = fmaxf(m0r, tmax0), mn1 = fmaxf(m1r, tmax1);
        float alp0 = (m0r == mn0) ? 1.0f : __expf(m0r - mn0);
        float alp1 = (m1r == mn1) ? 1.0f : __expf(m1r - mn1);

        uint32_t ph[8][2], pl[8][2];
        float rs0 = 0.0f, rs1 = 0.0f;
#pragma unroll
        for (int j = 0; j < 8; j++) {
            if (j <= jmax) {
                float p0 = (sacc[j][0] == NEGINF) ? 0.0f : __expf(sacc[j][0] - mn0);
                float p1 = (sacc[j][1] == NEGINF) ? 0.0f : __expf(sacc[j][1] - mn0);
                float p2 = (sacc[j][2] == NEGINF) ? 0.0f : __expf(sacc[j][2] - mn1);
                float p3 = (sacc[j][3] == NEGINF) ? 0.0f : __expf(sacc[j][3] - mn1);
                rs0 += p0 + p1; rs1 += p2 + p3;
                float h0 = __bfloat162float(__float2bfloat16(p0));
                float h1 = __bfloat162float(__float2bfloat16(p1));
                float h2 = __bfloat162float(__float2bfloat16(p2));
                float h3 = __bfloat162float(__float2bfloat16(p3));
                ph[j][0] = pack_bf16(h0, h1);
                ph[j][1] = pack_bf16(h2, h3);
                pl[j][0] = pack_bf16(p0 - h0, p1 - h1);
                pl[j][1] = pack_bf16(p2 - h2, p3 - h3);
            } else {
                ph[j][0] = ph[j][1] = pl[j][0] = pl[j][1] = 0u;
            }
        }
        rs0 += __shfl_xor_sync(0xffffffffu, rs0, 1);
        rs0 += __shfl_xor_sync(0xffffffffu, rs0, 2);
        rs1 += __shfl_xor_sync(0xffffffffu, rs1, 1);
        rs1 += __shfl_xor_sync(0xffffffffu, rs1, 2);

        l0r = l0r * alp0 + rs0;
        l1r = l1r * alp1 + rs1;
        m0r = mn0; m1r = mn1;
#pragma unroll
        for (int jo = 0; jo < 16; jo++) {
            oacc[jo][0] *= alp0; oacc[jo][1] *= alp0;
            oacc[jo][2] *= alp1; oacc[jo][3] *= alp1;
        }

        // ---- O += P V (3 split terms), V via ldmatrix.trans ----
        uint32_t vh_s = kvb + 32768u, vl_s = kvb + 49152u;
#pragma unroll
        for (int t = 0; t < 4; t++) {
            if (t <= gmax) {
                uint32_t a0h = ph[2 * t][0], a1h = ph[2 * t][1];
                uint32_t a2h = ph[2 * t + 1][0], a3h = ph[2 * t + 1][1];
                uint32_t a0l = pl[2 * t][0], a1l = pl[2 * t][1];
                uint32_t a2l = pl[2 * t + 1][0], a3l = pl[2 * t + 1][1];
                int r = t * 16 + rV0;
                int rsw = r & 7;
                uint32_t rbase = (uint32_t)((r >> 3) * 1024 + rsw * 128);
#pragma unroll
                for (int gg = 0; gg < 8; gg++) {
                    int sub = gg >> 2;
                    int c = (gg & 3) * 2 + (lane >> 4);
                    uint32_t off = (uint32_t)(sub * 8192) + rbase + (uint32_t)((c ^ rsw) << 4);
                    uint32_t v0, v1, v2, v3, w0, w1, w2, w3;
                    LDSM4T(v0, v1, v2, v3, vh_s + off);
                    LDSM4T(w0, w1, w2, w3, vl_s + off);
                    MMA16816(oacc[gg * 2],     a0h, a1h, a2h, a3h, v0, v1);
                    MMA16816(oacc[gg * 2],     a0l, a1l, a2l, a3l, v0, v1);
                    MMA16816(oacc[gg * 2],     a0h, a1h, a2h, a3h, w0, w1);
                    MMA16816(oacc[gg * 2 + 1], a0h, a1h, a2h, a3h, v2, v3);
                    MMA16816(oacc[gg * 2 + 1], a0l, a1l, a2l, a3l, v2, v3);
                    MMA16816(oacc[gg * 2 + 1], a0h, a1h, a2h, a3h, w2, w3);
                }
            }
        }
    }

    // epilogue: normalize, split to bf16 hi/lo for the Wo GEMM
    float inv0 = 1.0f / l0r, inv1 = 1.0f / l1r;
    size_t r0 = (size_t)(b * SS + qg0) * HIDN + h * DH + (lane & 3) * 2;
    size_t r1 = (size_t)(b * SS + qg1) * HIDN + h * DH + (lane & 3) * 2;
#pragma unroll
    for (int jo = 0; jo < 16; jo++) {
        int cofs = jo * 8;
        store_split2(ah_g + r0 + cofs, al_g + r0 + cofs, oacc[jo][0] * inv0, oacc[jo][1] * inv0);
        store_split2(ah_g + r1 + cofs, al_g + r1 + cofs, oacc[jo][2] * inv1, oacc[jo][3] * inv1);
    }
}

// ---------------- launch ----------------
extern "C" void kernel_launch(void* const* d_in, const int* in_sizes, int n_in,
                              void* d_out, int out_size)
{
    (void)in_sizes; (void)n_in; (void)out_size;
    const float* x  = (const float*)d_in[0];
    const float* Wq = (const float*)d_in[1];
    const float* Wk = (const float*)d_in[2];
    const float* Wv = (const float*)d_in[3];
    const float* Wo = (const float*)d_in[4];
    float* out = (float*)d_out;

    void *lmp, *xh, *xl, *qh, *ql, *kh, *kl, *vh, *vl, *ah, *al;
    void *wqh, *wql, *wkh, *wkl, *wvh, *wvl, *woh, *wol;
    cudaGetSymbolAddress(&lmp, g_lm);
    cudaGetSymbolAddress(&xh, g_xh);   cudaGetSymbolAddress(&xl, g_xl);
    cudaGetSymbolAddress(&qh, g_qh);   cudaGetSymbolAddress(&ql, g_ql);
    cudaGetSymbolAddress(&kh, g_kh);   cudaGetSymbolAddress(&kl, g_kl);
    cudaGetSymbolAddress(&vh, g_vh);   cudaGetSymbolAddress(&vl, g_vl);
    cudaGetSymbolAddress(&ah, g_ah);   cudaGetSymbolAddress(&al, g_al);
    cudaGetSymbolAddress(&wqh, g_wqh); cudaGetSymbolAddress(&wql, g_wql);
    cudaGetSymbolAddress(&wkh, g_wkh); cudaGetSymbolAddress(&wkl, g_wkl);
    cudaGetSymbolAddress(&wvh, g_wvh); cudaGetSymbolAddress(&wvl, g_wvl);
    cudaGetSymbolAddress(&woh, g_woh); cudaGetSymbolAddress(&wol, g_wol);

    // TLS mask pipeline
    mean_kernel <<<dim3(HIDN / 256, BB), 256>>>(x);
    mnorm_kernel<<<BB, 256>>>();
    score_kernel<<<dim3(SS, BB), 256>>>(x);
    topk_kernel <<<BB, 1024>>>();

    // operand prep
    xsplit_kernel<<<(MTOT * HIDN) / 256, 256>>>(x, (__nv_bfloat16*)xh, (__nv_bfloat16*)xl);
    wsplit_kernel<<<dim3(HIDN / 32, KDIM / 32), dim3(32, 8)>>>(Wq, (__nv_bfloat16*)wqh, (__nv_bfloat16*)wql, HIDN);
    wsplit_kernel<<<dim3(KVD  / 32, KDIM / 32), dim3(32, 8)>>>(Wk, (__nv_bfloat16*)wkh, (__nv_bfloat16*)wkl, KVD);
    wsplit_kernel<<<dim3(KVD  / 32, KDIM / 32), dim3(32, 8)>>>(Wv, (__nv_bfloat16*)wvh, (__nv_bfloat16*)wvl, KVD);
    wsplit_kernel<<<dim3(HIDN / 32, KDIM / 32), dim3(32, 8)>>>(Wo, (__nv_bfloat16*)woh, (__nv_bfloat16*)wol, HIDN);

    cudaFuncSetAttribute(bf16_gemm_kernel<true>,  cudaFuncAttributeMaxDynamicSharedMemorySize, GEMM_SMEM_BYTES);
    cudaFuncSetAttribute(bf16_gemm_kernel<false>, cudaFuncAttributeMaxDynamicSharedMemorySize, GEMM_SMEM_BYTES);
    cudaFuncSetAttribute(attn_mma_kernel, cudaFuncAttributeMaxDynamicSharedMemorySize, ATT_SMEM);

    // projections -> split bf16 outputs directly
    bf16_gemm_kernel<true><<<dim3(HIDN / 128, MTOT / 128), 256, GEMM_SMEM_BYTES>>>(
        (const __nv_bfloat16*)xh, (const __nv_bfloat16*)xl,
        (const __nv_bfloat16*)wqh, (const __nv_bfloat16*)wql,
        nullptr, (__nv_bfloat16*)qh, (__nv_bfloat16*)ql, HIDN);
    bf16_gemm_kernel<true><<<dim3(KVD / 128, MTOT / 128), 256, GEMM_SMEM_BYTES>>>(
        (const __nv_bfloat16*)xh, (const __nv_bfloat16*)xl,
        (const __nv_bfloat16*)wkh, (const __nv_bfloat16*)wkl,
        nullptr, (__nv_bfloat16*)kh, (__nv_bfloat16*)kl, KVD);
    bf16_gemm_kernel<true><<<dim3(KVD / 128, MTOT / 128), 256, GEMM_SMEM_BYTES>>>(
        (const __nv_bfloat16*)xh, (const __nv_bfloat16*)xl,
        (const __nv_bfloat16*)wvh, (const __nv_bfloat16*)wvl,
        nullptr, (__nv_bfloat16*)vh, (__nv_bfloat16*)vl, KVD);

    // attention (split bf16 mma), writes split output for Wo GEMM
    attn_mma_kernel<<<dim3(SS / 128, BB * NH), 256, ATT_SMEM>>>(
        (const __nv_bfloat16*)qh, (const __nv_bfloat16*)ql,
        (const __nv_bfloat16*)kh, (const __nv_bfloat16*)kl,
        (const __nv_bfloat16*)vh, (const __nv_bfloat16*)vl,
        (const int*)lmp, (__nv_bfloat16*)ah, (__nv_bfloat16*)al);

    // output projection -> f32
    bf16_gemm_kernel<false><<<dim3(HIDN / 128, MTOT / 128), 256, GEMM_SMEM_BYTES>>>(
        (const __nv_bfloat16*)ah, (const __nv_bfloat16*)al,
        (const __nv_bfloat16*)woh, (const __nv_bfloat16*)wol,
        out, nullptr, nullptr, HIDN);
}